// round 4
// baseline (speedup 1.0000x reference)
#include <cuda_runtime.h>
#include <cstdint>

#define THREADS 256
#define NWARP (THREADS / 32)
#define TOPK 5
#define NCAT 8
#define FULLM 0xffffffffu
#define L2E 1.4426950408889634f
#define LN2 0.6931471805599453f
#define NEG_INF (-__int_as_float(0x7f800000))

__device__ float g_rowloss[8192];
__device__ unsigned int g_done = 0;

__device__ __forceinline__ float ex2f(float x) {
    float y; asm("ex2.approx.ftz.f32 %0, %1;" : "=f"(y) : "f"(x)); return y;
}
__device__ __forceinline__ float lg2f(float x) {
    float y; asm("lg2.approx.ftz.f32 %0, %1;" : "=f"(y) : "f"(x)); return y;
}
__device__ __forceinline__ uint64_t pk2(float lo, float hi) {
    uint64_t r; asm("mov.b64 %0, {%1, %2};" : "=l"(r) : "f"(lo), "f"(hi)); return r;
}
__device__ __forceinline__ void upk2(uint64_t v, float& lo, float& hi) {
    asm("mov.b64 {%0, %1}, %2;" : "=f"(lo), "=f"(hi) : "l"(v));
}
__device__ __forceinline__ uint64_t ffma2(uint64_t a, uint64_t b, uint64_t c) {
    uint64_t d; asm("fma.rn.f32x2 %0, %1, %2, %3;" : "=l"(d) : "l"(a), "l"(b), "l"(c));
    return d;
}

__device__ __forceinline__ void insert5(float (&tv)[TOPK], int (&ti)[TOPK], float v, int idx) {
    tv[TOPK - 1] = v; ti[TOPK - 1] = idx;
#pragma unroll
    for (int k = TOPK - 1; k > 0; --k) {
        if (tv[k] > tv[k - 1]) {
            float tf = tv[k]; tv[k] = tv[k - 1]; tv[k - 1] = tf;
            int   tt = ti[k]; ti[k] = ti[k - 1]; ti[k - 1] = tt;
        }
    }
}

__global__ void __launch_bounds__(THREADS)
hier_loss_fused(const float* __restrict__ logits,
                const int* __restrict__ labels,
                const int* __restrict__ catlab,
                const int* __restrict__ c2c,
                float* __restrict__ out,
                int V, int ncmd, int B)
{
    const int b    = blockIdx.x;
    const int tid  = threadIdx.x;
    const int lane = tid & 31;
    const int w    = tid >> 5;
    const float* row = logits + (size_t)b * (size_t)V;

    __shared__ int   s_c2c[64];
    __shared__ float s_wC[NWARP], s_wS[NWARP];
    __shared__ float s_wTv[NWARP][TOPK];
    __shared__ int   s_wTi[NWARP][TOPK];
    __shared__ float s_cat[NCAT];
    __shared__ int   s_isLast;
    __shared__ float s_red[THREADS];

    if (tid < 64 && tid < ncmd) s_c2c[tid] = c2c[tid];

    // warp-replicated top-5
    float tv[TOPK]; int ti[TOPK];
#pragma unroll
    for (int k = 0; k < TOPK; ++k) { tv[k] = NEG_INF; ti[k] = 0; }

    float x0   = __ldg(row);
    float negC = -x0 * L2E;                 // per-thread base (log2 domain)
    float s0 = 0.f, s1 = 0.f, s2 = 0.f, s3 = 0.f;

    const int mis = (int)(((size_t)b * (size_t)V) & 3);
    const int pre = (4 - mis) & 3;
    const int nv4 = (V - pre) >> 2;
    const int nIterV = nv4 / (4 * THREADS);
    const int vecElems = nIterV * 16 * THREADS;
    const float4* __restrict__ p4 = (const float4*)(row + pre) + tid;

    // ---- head (pre <= 3 elements) ----
    {
        bool valid = (tid < pre);
        float x = valid ? __ldg(row + tid) : NEG_INF;
        unsigned bal = __ballot_sync(FULLM, x > tv[TOPK - 1]);
        while (bal) {
            int L = __ffs(bal) - 1; bal &= bal - 1;
            float xv = __shfl_sync(FULLM, x, L);
            if (xv > tv[TOPK - 1]) insert5(tv, ti, xv, (w << 5) + L);
        }
        float d = fmaf(x, L2E, negC);
        if (d > 60.0f) { negC = 40.0f - x * L2E; d = fmaf(x, L2E, negC); }  // s==0, no scale
        s0 += ex2f(d);
        // establish invariant: tv[0]*L2E + negC <= 60 for this lane
        if (fmaf(tv[0], L2E, negC) > 60.0f) {
            float nn = 40.0f - tv[0] * L2E;
            float sc = ex2f(nn - negC);
            s0 *= sc; negC = nn;
        }
    }
    uint64_t L2E2  = pk2(L2E, L2E);
    uint64_t negC2 = pk2(negC, negC);

    // cold insert helper per quad
#define INS_QUAD(v, qm, f4off)                                                \
    do {                                                                      \
        unsigned bal = __ballot_sync(FULLM, (qm) > tv[TOPK - 1]);             \
        while (bal) {                                                         \
            int L = __ffs(bal) - 1; bal &= bal - 1;                           \
            float a0 = __shfl_sync(FULLM, (v).x, L);                          \
            float a1 = __shfl_sync(FULLM, (v).y, L);                          \
            float a2 = __shfl_sync(FULLM, (v).z, L);                          \
            float a3 = __shfl_sync(FULLM, (v).w, L);                          \
            int bi = pre + 4 * ((f4off) + (w << 5) + L);                      \
            if (a0 > tv[TOPK - 1]) insert5(tv, ti, a0, bi + 0);               \
            if (a1 > tv[TOPK - 1]) insert5(tv, ti, a1, bi + 1);               \
            if (a2 > tv[TOPK - 1]) insert5(tv, ti, a2, bi + 2);               \
            if (a3 > tv[TOPK - 1]) insert5(tv, ti, a3, bi + 3);               \
        }                                                                     \
    } while (0)

    // ---- main vector loop: 4 x float4 = 16 elements / thread / iter ----
    int jbase = 0;
    for (int j = 0; j < nIterV; ++j) {
        float4 v0 = __ldg(p4);
        float4 v1 = __ldg(p4 + THREADS);
        float4 v2 = __ldg(p4 + 2 * THREADS);
        float4 v3 = __ldg(p4 + 3 * THREADS);
        p4 += 4 * THREADS;

        // raw-value max tree (alu pipe) for the warp top-5 filter
        float q0 = fmaxf(fmaxf(v0.x, v0.y), fmaxf(v0.z, v0.w));
        float q1 = fmaxf(fmaxf(v1.x, v1.y), fmaxf(v1.z, v1.w));
        float q2 = fmaxf(fmaxf(v2.x, v2.y), fmaxf(v2.z, v2.w));
        float q3 = fmaxf(fmaxf(v3.x, v3.y), fmaxf(v3.z, v3.w));
        float imax = fmaxf(fmaxf(q0, q1), fmaxf(q2, q3));

        // single divergence region per iteration
        if (__any_sync(FULLM, imax > tv[TOPK - 1])) {
            INS_QUAD(v0, q0, jbase);
            INS_QUAD(v1, q1, jbase + THREADS);
            INS_QUAD(v2, q2, jbase + 2 * THREADS);
            INS_QUAD(v3, q3, jbase + 3 * THREADS);
            // maintain invariant so the exp path below cannot overflow
            if (fmaf(tv[0], L2E, negC) > 60.0f) {
                float nn = 40.0f - tv[0] * L2E;
                float sc = ex2f(nn - negC);
                s0 *= sc; s1 *= sc; s2 *= sc; s3 *= sc;
                negC = nn; negC2 = pk2(negC, negC);
            }
        }

        // exp accumulation: packed FFMA2 + MUFU + scalar FADD
        uint64_t dA = ffma2(pk2(v0.x, v0.y), L2E2, negC2);
        uint64_t dB = ffma2(pk2(v0.z, v0.w), L2E2, negC2);
        uint64_t dC = ffma2(pk2(v1.x, v1.y), L2E2, negC2);
        uint64_t dD = ffma2(pk2(v1.z, v1.w), L2E2, negC2);
        uint64_t dE = ffma2(pk2(v2.x, v2.y), L2E2, negC2);
        uint64_t dF = ffma2(pk2(v2.z, v2.w), L2E2, negC2);
        uint64_t dG = ffma2(pk2(v3.x, v3.y), L2E2, negC2);
        uint64_t dH = ffma2(pk2(v3.z, v3.w), L2E2, negC2);
        float a0, a1;
        upk2(dA, a0, a1); s0 += ex2f(a0); s1 += ex2f(a1);
        upk2(dB, a0, a1); s2 += ex2f(a0); s3 += ex2f(a1);
        upk2(dC, a0, a1); s0 += ex2f(a0); s1 += ex2f(a1);
        upk2(dD, a0, a1); s2 += ex2f(a0); s3 += ex2f(a1);
        upk2(dE, a0, a1); s0 += ex2f(a0); s1 += ex2f(a1);
        upk2(dF, a0, a1); s2 += ex2f(a0); s3 += ex2f(a1);
        upk2(dG, a0, a1); s0 += ex2f(a0); s1 += ex2f(a1);
        upk2(dH, a0, a1); s2 += ex2f(a0); s3 += ex2f(a1);

        jbase += 4 * THREADS;
    }
#undef INS_QUAD

    // ---- scalar tail: [pre + vecElems, V) ----
    for (int i0 = pre + vecElems; i0 < V; i0 += THREADS) {
        int i = i0 + tid;
        bool valid = (i < V);
        float x = valid ? __ldg(row + i) : NEG_INF;
        unsigned bal = __ballot_sync(FULLM, x > tv[TOPK - 1]);
        if (bal) {
            do {
                int L = __ffs(bal) - 1; bal &= bal - 1;
                float xv = __shfl_sync(FULLM, x, L);
                if (xv > tv[TOPK - 1]) insert5(tv, ti, xv, i0 + (w << 5) + L);
            } while (bal);
            if (fmaf(tv[0], L2E, negC) > 60.0f) {
                float nn = 40.0f - tv[0] * L2E;
                float sc = ex2f(nn - negC);
                s0 *= sc; s1 *= sc; s2 *= sc; s3 *= sc;
                negC = nn;
            }
        }
        s0 += ex2f(fmaf(x, L2E, negC));
    }

    // ---- warp reduce (C, s) ----
    float s = (s0 + s1) + (s2 + s3);
    float C = -negC;
#pragma unroll
    for (int off = 16; off; off >>= 1) {
        float Co = __shfl_xor_sync(FULLM, C, off);
        float so = __shfl_xor_sync(FULLM, s, off);
        float Cn = fmaxf(C, Co);
        s = s * ex2f(C - Cn) + so * ex2f(Co - Cn);
        C = Cn;
    }

    if (lane == 0) {
        s_wC[w] = C; s_wS[w] = s;
#pragma unroll
        for (int k = 0; k < TOPK; ++k) { s_wTv[w][k] = tv[k]; s_wTi[w][k] = ti[k]; }
    }
    __syncthreads();

    if (tid == 0) {
        float Cf = s_wC[0], sf = s_wS[0];
        for (int ww = 1; ww < NWARP; ++ww) {
            float Co = s_wC[ww], so = s_wS[ww];
            float Cn = fmaxf(Cf, Co);
            sf = sf * ex2f(Cf - Cn) + so * ex2f(Co - Cn);
            Cf = Cn;
        }
        float ftv[TOPK]; int fti[TOPK];
#pragma unroll
        for (int k = 0; k < TOPK; ++k) { ftv[k] = s_wTv[0][k]; fti[k] = s_wTi[0][k]; }
        for (int ww = 1; ww < NWARP; ++ww) {
            for (int k = 0; k < TOPK; ++k) {
                float v = s_wTv[ww][k];
                if (v > ftv[TOPK - 1]) insert5(ftv, fti, v, s_wTi[ww][k]);
                else break;
            }
        }

        float lse  = (Cf + lg2f(sf)) * LN2;
        int   lab  = __ldg(labels + b);
        float xlab = __ldg(row + lab);
        float nll_cmd = lse - xlab;

#pragma unroll
        for (int c = 0; c < NCAT; ++c) s_cat[c] = 0.0f;
#pragma unroll
        for (int k = 0; k < TOPK; ++k)
            s_cat[s_c2c[fti[k] % ncmd]] += ftv[k];

        float mxc = s_cat[0];
#pragma unroll
        for (int c = 1; c < NCAT; ++c) mxc = fmaxf(mxc, s_cat[c]);
        float ssum = 0.0f;
#pragma unroll
        for (int c = 0; c < NCAT; ++c) ssum += ex2f((s_cat[c] - mxc) * L2E);
        int   cl = __ldg(catlab + b);
        float nll_cat = lg2f(ssum) * LN2 + mxc - s_cat[cl];

        g_rowloss[b] = 0.6f * nll_cmd + 0.4f * nll_cat;

        __threadfence();
        unsigned int prev = atomicAdd(&g_done, 1u);
        s_isLast = (prev == (unsigned int)(gridDim.x - 1));
    }
    __syncthreads();

    if (s_isLast) {
        __threadfence();
        float a = 0.0f;
        for (int i = tid; i < B; i += THREADS) a += g_rowloss[i];
        s_red[tid] = a;
        __syncthreads();
#pragma unroll
        for (int off = THREADS / 2; off; off >>= 1) {
            if (tid < off) s_red[tid] += s_red[tid + off];
            __syncthreads();
        }
        if (tid == 0) {
            out[0] = s_red[0] * (1.0f / (float)B);
            atomicExch(&g_done, 0u);
        }
    }
}

extern "C" void kernel_launch(void* const* d_in, const int* in_sizes, int n_in,
                              void* d_out, int out_size)
{
    const float* logits = (const float*)d_in[0];
    const int*   labels = (const int*)d_in[1];
    const int*   catlab = (const int*)d_in[2];
    const int*   c2c    = (const int*)d_in[3];

    const int B    = in_sizes[1];
    const int V    = in_sizes[0] / B;
    const int ncmd = in_sizes[3];

    hier_loss_fused<<<B, THREADS>>>(logits, labels, catlab, c2c,
                                    (float*)d_out, V, ncmd, B);
}

// round 6
// speedup vs baseline: 1.0658x; 1.0658x over previous
#include <cuda_runtime.h>

#define THREADS 256
#define NWARP (THREADS / 32)
#define TOPK 5
#define NCAT 8
#define FULLM 0xffffffffu
#define L2E 1.4426950408889634f
#define LN2 0.6931471805599453f
#define NEG_INF (-__int_as_float(0x7f800000))

__device__ float g_rowloss[8192];
__device__ unsigned int g_done = 0;

__device__ __forceinline__ float ex2f(float x) {
    float y; asm("ex2.approx.ftz.f32 %0, %1;" : "=f"(y) : "f"(x)); return y;
}
__device__ __forceinline__ float lg2f(float x) {
    float y; asm("lg2.approx.ftz.f32 %0, %1;" : "=f"(y) : "f"(x)); return y;
}

__device__ __forceinline__ void insert5(float (&tv)[TOPK], int (&ti)[TOPK], float v, int idx) {
    tv[TOPK - 1] = v; ti[TOPK - 1] = idx;
#pragma unroll
    for (int k = TOPK - 1; k > 0; --k) {
        if (tv[k] > tv[k - 1]) {
            float tf = tv[k]; tv[k] = tv[k - 1]; tv[k - 1] = tf;
            int   tt = ti[k]; ti[k] = ti[k - 1]; ti[k - 1] = tt;
        }
    }
}

__global__ void __launch_bounds__(THREADS, 6)
hier_loss_fused(const float* __restrict__ logits,
                const int* __restrict__ labels,
                const int* __restrict__ catlab,
                const int* __restrict__ c2c,
                float* __restrict__ out,
                int V, int ncmd, int B)
{
    const int b    = blockIdx.x;
    const int tid  = threadIdx.x;
    const int lane = tid & 31;
    const int w    = tid >> 5;
    const float* row = logits + (size_t)b * (size_t)V;

    __shared__ int   s_c2c[64];
    __shared__ float s_wC[NWARP], s_wS[NWARP];
    __shared__ float s_wTv[NWARP][TOPK];
    __shared__ int   s_wTi[NWARP][TOPK];
    __shared__ float s_cat[NCAT];
    __shared__ int   s_isLast;
    __shared__ float s_red[THREADS];

    if (tid < 64 && tid < ncmd) s_c2c[tid] = c2c[tid];

    // warp-replicated top-5 (identical across lanes of a warp)
    float tv[TOPK]; int ti[TOPK];
#pragma unroll
    for (int k = 0; k < TOPK; ++k) { tv[k] = NEG_INF; ti[k] = 0; }

    float x0   = __ldg(row);
    float negC = -x0 * L2E;                 // base in log2 domain
    float s0 = 0.f, s1 = 0.f;

    const int mis = (int)(((size_t)b * (size_t)V) & 3);
    const int pre = (4 - mis) & 3;
    const int nv4 = (V - pre) >> 2;
    const int nIterV = nv4 / (2 * THREADS);         // 2 x float4 per thread per iter
    const int vecElems = nIterV * 8 * THREADS;
    const float4* __restrict__ p4 = (const float4*)(row + pre) + tid;

    // ---- head (pre <= 3 elements) ----
    {
        bool valid = (tid < pre);
        float x = valid ? __ldg(row + tid) : NEG_INF;
        unsigned bal = __ballot_sync(FULLM, x > tv[TOPK - 1]);
        while (bal) {
            int L = __ffs(bal) - 1; bal &= bal - 1;
            float xv = __shfl_sync(FULLM, x, L);
            if (xv > tv[TOPK - 1]) insert5(tv, ti, xv, (w << 5) + L);
        }
        float d = fmaf(x, L2E, negC);
        if (d > 60.0f) { negC = 40.0f - x * L2E; d = fmaf(x, L2E, negC); }
        s0 += ex2f(d);
        if (fmaf(tv[0], L2E, negC) > 60.0f) {
            float nn = 40.0f - tv[0] * L2E;
            float sc = ex2f(nn - negC);
            s0 *= sc; negC = nn;
        }
    }

    // cold insert helper per quad
#define INS_QUAD(v, qm, f4off)                                                \
    do {                                                                      \
        unsigned bal = __ballot_sync(FULLM, (qm) > tv[TOPK - 1]);             \
        while (bal) {                                                         \
            int L = __ffs(bal) - 1; bal &= bal - 1;                           \
            float a0 = __shfl_sync(FULLM, (v).x, L);                          \
            float a1 = __shfl_sync(FULLM, (v).y, L);                          \
            float a2 = __shfl_sync(FULLM, (v).z, L);                          \
            float a3 = __shfl_sync(FULLM, (v).w, L);                          \
            int bi = pre + 4 * ((f4off) + (w << 5) + L);                      \
            if (a0 > tv[TOPK - 1]) insert5(tv, ti, a0, bi + 0);               \
            if (a1 > tv[TOPK - 1]) insert5(tv, ti, a1, bi + 1);               \
            if (a2 > tv[TOPK - 1]) insert5(tv, ti, a2, bi + 2);               \
            if (a3 > tv[TOPK - 1]) insert5(tv, ti, a3, bi + 3);               \
        }                                                                     \
    } while (0)

    // ---- main vector loop: 2 x float4 = 8 elements / thread / iter ----
    int jbase = 0;
    for (int j = 0; j < nIterV; ++j) {
        float4 v0 = __ldg(p4);
        float4 v1 = __ldg(p4 + THREADS);
        p4 += 2 * THREADS;

        float q0 = fmaxf(fmaxf(v0.x, v0.y), fmaxf(v0.z, v0.w));
        float q1 = fmaxf(fmaxf(v1.x, v1.y), fmaxf(v1.z, v1.w));
        float imax = fmaxf(q0, q1);

        // single divergence region per iteration (rare)
        if (__any_sync(FULLM, imax > tv[TOPK - 1])) {
            INS_QUAD(v0, q0, jbase);
            INS_QUAD(v1, q1, jbase + THREADS);
            // maintain overflow invariant for the hot exp path
            if (fmaf(tv[0], L2E, negC) > 60.0f) {
                float nn = 40.0f - tv[0] * L2E;
                float sc = ex2f(nn - negC);
                s0 *= sc; s1 *= sc;
                negC = nn;
            }
        }

        s0 += ex2f(fmaf(v0.x, L2E, negC));
        s1 += ex2f(fmaf(v0.y, L2E, negC));
        s0 += ex2f(fmaf(v0.z, L2E, negC));
        s1 += ex2f(fmaf(v0.w, L2E, negC));
        s0 += ex2f(fmaf(v1.x, L2E, negC));
        s1 += ex2f(fmaf(v1.y, L2E, negC));
        s0 += ex2f(fmaf(v1.z, L2E, negC));
        s1 += ex2f(fmaf(v1.w, L2E, negC));

        jbase += 2 * THREADS;
    }
#undef INS_QUAD

    // ---- scalar tail: [pre + vecElems, V) ----
    for (int i0 = pre + vecElems; i0 < V; i0 += THREADS) {
        int i = i0 + tid;
        bool valid = (i < V);
        float x = valid ? __ldg(row + i) : NEG_INF;
        unsigned bal = __ballot_sync(FULLM, x > tv[TOPK - 1]);
        if (bal) {
            do {
                int L = __ffs(bal) - 1; bal &= bal - 1;
                float xv = __shfl_sync(FULLM, x, L);
                if (xv > tv[TOPK - 1]) insert5(tv, ti, xv, i0 + (w << 5) + L);
            } while (bal);
            if (fmaf(tv[0], L2E, negC) > 60.0f) {
                float nn = 40.0f - tv[0] * L2E;
                float sc = ex2f(nn - negC);
                s0 *= sc; s1 *= sc;
                negC = nn;
            }
        }
        s0 += ex2f(fmaf(x, L2E, negC));
    }

    // ---- warp reduce (C, s) ----
    float s = s0 + s1;
    float C = -negC;
#pragma unroll
    for (int off = 16; off; off >>= 1) {
        float Co = __shfl_xor_sync(FULLM, C, off);
        float so = __shfl_xor_sync(FULLM, s, off);
        float Cn = fmaxf(C, Co);
        s = s * ex2f(C - Cn) + so * ex2f(Co - Cn);
        C = Cn;
    }

    if (lane == 0) {
        s_wC[w] = C; s_wS[w] = s;
#pragma unroll
        for (int k = 0; k < TOPK; ++k) { s_wTv[w][k] = tv[k]; s_wTi[w][k] = ti[k]; }
    }
    __syncthreads();

    if (tid == 0) {
        float Cf = s_wC[0], sf = s_wS[0];
        for (int ww = 1; ww < NWARP; ++ww) {
            float Co = s_wC[ww], so = s_wS[ww];
            float Cn = fmaxf(Cf, Co);
            sf = sf * ex2f(Cf - Cn) + so * ex2f(Co - Cn);
            Cf = Cn;
        }
        float ftv[TOPK]; int fti[TOPK];
#pragma unroll
        for (int k = 0; k < TOPK; ++k) { ftv[k] = s_wTv[0][k]; fti[k] = s_wTi[0][k]; }
        for (int ww = 1; ww < NWARP; ++ww) {
            for (int k = 0; k < TOPK; ++k) {
                float v = s_wTv[ww][k];
                if (v > ftv[TOPK - 1]) insert5(ftv, fti, v, s_wTi[ww][k]);
                else break;
            }
        }

        float lse  = (Cf + lg2f(sf)) * LN2;
        int   lab  = __ldg(labels + b);
        float xlab = __ldg(row + lab);
        float nll_cmd = lse - xlab;

#pragma unroll
        for (int c = 0; c < NCAT; ++c) s_cat[c] = 0.0f;
#pragma unroll
        for (int k = 0; k < TOPK; ++k)
            s_cat[s_c2c[fti[k] % ncmd]] += ftv[k];

        float mxc = s_cat[0];
#pragma unroll
        for (int c = 1; c < NCAT; ++c) mxc = fmaxf(mxc, s_cat[c]);
        float ssum = 0.0f;
#pragma unroll
        for (int c = 0; c < NCAT; ++c) ssum += ex2f((s_cat[c] - mxc) * L2E);
        int   cl = __ldg(catlab + b);
        float nll_cat = lg2f(ssum) * LN2 + mxc - s_cat[cl];

        g_rowloss[b] = 0.6f * nll_cmd + 0.4f * nll_cat;

        __threadfence();
        unsigned int prev = atomicAdd(&g_done, 1u);
        s_isLast = (prev == (unsigned int)(gridDim.x - 1));
    }
    __syncthreads();

    if (s_isLast) {
        __threadfence();
        float a = 0.0f;
        for (int i = tid; i < B; i += THREADS) a += g_rowloss[i];
        s_red[tid] = a;
        __syncthreads();
#pragma unroll
        for (int off = THREADS / 2; off; off >>= 1) {
            if (tid < off) s_red[tid] += s_red[tid + off];
            __syncthreads();
        }
        if (tid == 0) {
            out[0] = s_red[0] * (1.0f / (float)B);
            atomicExch(&g_done, 0u);
        }
    }
}

extern "C" void kernel_launch(void* const* d_in, const int* in_sizes, int n_in,
                              void* d_out, int out_size)
{
    const float* logits = (const float*)d_in[0];
    const int*   labels = (const int*)d_in[1];
    const int*   catlab = (const int*)d_in[2];
    const int*   c2c    = (const int*)d_in[3];

    const int B    = in_sizes[1];
    const int V    = in_sizes[0] / B;
    const int ncmd = in_sizes[3];

    hier_loss_fused<<<B, THREADS>>>(logits, labels, catlab, c2c,
                                    (float*)d_out, V, ncmd, B);
}

// round 7
// speedup vs baseline: 1.3834x; 1.2980x over previous
#include <cuda_runtime.h>

#define THREADS 256
#define NWARP (THREADS / 32)
#define TOPK 5
#define NCAT 8
#define CAP 512
#define FULLM 0xffffffffu
#define L2E 1.4426950408889634f
#define LN2 0.6931471805599453f
#define NEG_INF (-__int_as_float(0x7f800000))
#define THRESH 3.25f

__device__ float g_rowloss[8192];
__device__ unsigned int g_done = 0;

__device__ __forceinline__ float ex2f(float x) {
    float y; asm("ex2.approx.ftz.f32 %0, %1;" : "=f"(y) : "f"(x)); return y;
}
__device__ __forceinline__ float lg2f(float x) {
    float y; asm("lg2.approx.ftz.f32 %0, %1;" : "=f"(y) : "f"(x)); return y;
}

__device__ __forceinline__ void insert5(float (&tv)[TOPK], int (&ti)[TOPK], float v, int idx) {
    tv[TOPK - 1] = v; ti[TOPK - 1] = idx;
#pragma unroll
    for (int k = TOPK - 1; k > 0; --k) {
        if (tv[k] > tv[k - 1]) {
            float tf = tv[k]; tv[k] = tv[k - 1]; tv[k - 1] = tf;
            int   tt = ti[k]; ti[k] = ti[k - 1]; ti[k - 1] = tt;
        }
    }
}

__global__ void __launch_bounds__(THREADS, 6)
hier_loss_fused(const float* __restrict__ logits,
                const int* __restrict__ labels,
                const int* __restrict__ catlab,
                const int* __restrict__ c2c,
                float* __restrict__ out,
                int V, int ncmd, int B)
{
    const int b    = blockIdx.x;
    const int tid  = threadIdx.x;
    const int lane = tid & 31;
    const int w    = tid >> 5;
    const float* row = logits + (size_t)b * (size_t)V;

    __shared__ int   s_c2c[64];
    __shared__ float s_wC[NWARP], s_wS[NWARP];
    __shared__ float s_vals[CAP];
    __shared__ int   s_idx[CAP];
    __shared__ int   s_cnt;
    __shared__ float s_cat[NCAT];
    __shared__ int   s_isLast;
    __shared__ float s_red[THREADS];

    if (tid < 64 && tid < ncmd) s_c2c[tid] = c2c[tid];
    if (tid == 0) s_cnt = 0;
    __syncthreads();

    float x0   = __ldg(row);
    float negC = -x0 * L2E;                 // fixed base (log2 domain)
    float s0 = 0.f, s1 = 0.f, s2 = 0.f, s3 = 0.f;

    const int mis = (int)(((size_t)b * (size_t)V) & 3);
    const int pre = (4 - mis) & 3;
    const int nv4 = (V - pre) >> 2;
    const int nIterV = nv4 / (4 * THREADS);         // 4 x float4 per thread per iter
    const int vecElems = nIterV * 16 * THREADS;
    const float4* __restrict__ p4 = (const float4*)(row + pre) + tid;

#define PUSH(val, ei)                                                         \
    do {                                                                      \
        if ((val) > THRESH) {                                                 \
            int pos = atomicAdd(&s_cnt, 1);                                   \
            if (pos < CAP) { s_vals[pos] = (val); s_idx[pos] = (ei); }        \
        }                                                                     \
    } while (0)

    // ---- head (pre <= 3 elements) ----
    if (tid < pre) {
        float x = __ldg(row + tid);
        s0 += ex2f(fmaf(x, L2E, negC));
        PUSH(x, tid);
    }

    // ---- main vector loop: 4 x float4 = 16 elements / thread / iter ----
    int jbase = 0;
    for (int j = 0; j < nIterV; ++j) {
        float4 v0 = __ldg(p4);
        float4 v1 = __ldg(p4 + THREADS);
        float4 v2 = __ldg(p4 + 2 * THREADS);
        float4 v3 = __ldg(p4 + 3 * THREADS);
        p4 += 4 * THREADS;

        float q0 = fmaxf(fmaxf(v0.x, v0.y), fmaxf(v0.z, v0.w));
        float q1 = fmaxf(fmaxf(v1.x, v1.y), fmaxf(v1.z, v1.w));
        float q2 = fmaxf(fmaxf(v2.x, v2.y), fmaxf(v2.z, v2.w));
        float q3 = fmaxf(fmaxf(v3.x, v3.y), fmaxf(v3.z, v3.w));
        float imax = fmaxf(fmaxf(q0, q1), fmaxf(q2, q3));

        // rare candidate-collection region (fixed threshold: no coupling)
        if (__any_sync(FULLM, imax > THRESH)) {
            if (imax > THRESH) {
                int bi0 = pre + 4 * (jbase + tid);
                int bi1 = bi0 + 4 * THREADS;
                int bi2 = bi0 + 8 * THREADS;
                int bi3 = bi0 + 12 * THREADS;
                PUSH(v0.x, bi0 + 0); PUSH(v0.y, bi0 + 1);
                PUSH(v0.z, bi0 + 2); PUSH(v0.w, bi0 + 3);
                PUSH(v1.x, bi1 + 0); PUSH(v1.y, bi1 + 1);
                PUSH(v1.z, bi1 + 2); PUSH(v1.w, bi1 + 3);
                PUSH(v2.x, bi2 + 0); PUSH(v2.y, bi2 + 1);
                PUSH(v2.z, bi2 + 2); PUSH(v2.w, bi2 + 3);
                PUSH(v3.x, bi3 + 0); PUSH(v3.y, bi3 + 1);
                PUSH(v3.z, bi3 + 2); PUSH(v3.w, bi3 + 3);
            }
        }

        // hot exp-sum: FFMA + MUFU + FADD per element
        s0 += ex2f(fmaf(v0.x, L2E, negC));
        s1 += ex2f(fmaf(v0.y, L2E, negC));
        s2 += ex2f(fmaf(v0.z, L2E, negC));
        s3 += ex2f(fmaf(v0.w, L2E, negC));
        s0 += ex2f(fmaf(v1.x, L2E, negC));
        s1 += ex2f(fmaf(v1.y, L2E, negC));
        s2 += ex2f(fmaf(v1.z, L2E, negC));
        s3 += ex2f(fmaf(v1.w, L2E, negC));
        s0 += ex2f(fmaf(v2.x, L2E, negC));
        s1 += ex2f(fmaf(v2.y, L2E, negC));
        s2 += ex2f(fmaf(v2.z, L2E, negC));
        s3 += ex2f(fmaf(v2.w, L2E, negC));
        s0 += ex2f(fmaf(v3.x, L2E, negC));
        s1 += ex2f(fmaf(v3.y, L2E, negC));
        s2 += ex2f(fmaf(v3.z, L2E, negC));
        s3 += ex2f(fmaf(v3.w, L2E, negC));

        jbase += 4 * THREADS;
    }

    // ---- scalar tail: [pre + vecElems, V) ----
    for (int i = pre + vecElems + tid; i < V; i += THREADS) {
        float x = __ldg(row + i);
        s0 += ex2f(fmaf(x, L2E, negC));
        PUSH(x, i);
    }
#undef PUSH

    // ---- warp reduce s (common base negC for all threads in block) ----
    float s = (s0 + s1) + (s2 + s3);
#pragma unroll
    for (int off = 16; off; off >>= 1)
        s += __shfl_xor_sync(FULLM, s, off);

    if (lane == 0) { s_wC[w] = -negC; s_wS[w] = s; }
    __syncthreads();

    // ---- warp 0: top-5 selection + final math ----
    if (w == 0) {
        float tv[TOPK]; int ti[TOPK];
#pragma unroll
        for (int k = 0; k < TOPK; ++k) { tv[k] = NEG_INF; ti[k] = 0; }

        int cnt = s_cnt;
        if (cnt >= TOPK && cnt <= CAP) {
            // select from the small candidate buffer
            for (int base = 0; base < cnt; base += 32) {
                int i = base + lane;
                float x = (i < cnt) ? s_vals[i] : NEG_INF;
                int  id = (i < cnt) ? s_idx[i]  : 0;
                unsigned bal = __ballot_sync(FULLM, x > tv[TOPK - 1]);
                while (bal) {
                    int L = __ffs(bal) - 1; bal &= bal - 1;
                    float xv = __shfl_sync(FULLM, x, L);
                    int   iv = __shfl_sync(FULLM, id, L);
                    if (xv > tv[TOPK - 1]) insert5(tv, ti, xv, iv);
                }
            }
        } else {
            // exact fallback (astronomically rare): full-row online top-5
            for (int i0 = 0; i0 < V; i0 += 32) {
                int i = i0 + lane;
                float x = (i < V) ? __ldg(row + i) : NEG_INF;
                unsigned bal = __ballot_sync(FULLM, x > tv[TOPK - 1]);
                while (bal) {
                    int L = __ffs(bal) - 1; bal &= bal - 1;
                    float xv = __shfl_sync(FULLM, x, L);
                    if (xv > tv[TOPK - 1]) insert5(tv, ti, xv, i0 + L);
                }
            }
        }

        if (lane == 0) {
            // combine block exp-sum (all warps share the same base)
            float Cf = s_wC[0];
            float sf = 0.0f;
            for (int ww = 0; ww < NWARP; ++ww) sf += s_wS[ww];

            float lse  = (Cf + lg2f(sf)) * LN2;
            int   lab  = __ldg(labels + b);
            float xlab = __ldg(row + lab);
            float nll_cmd = lse - xlab;

#pragma unroll
            for (int c = 0; c < NCAT; ++c) s_cat[c] = 0.0f;
#pragma unroll
            for (int k = 0; k < TOPK; ++k)
                s_cat[s_c2c[ti[k] % ncmd]] += tv[k];

            float mxc = s_cat[0];
#pragma unroll
            for (int c = 1; c < NCAT; ++c) mxc = fmaxf(mxc, s_cat[c]);
            float ssum = 0.0f;
#pragma unroll
            for (int c = 0; c < NCAT; ++c) ssum += ex2f((s_cat[c] - mxc) * L2E);
            int   cl = __ldg(catlab + b);
            float nll_cat = lg2f(ssum) * LN2 + mxc - s_cat[cl];

            g_rowloss[b] = 0.6f * nll_cmd + 0.4f * nll_cat;

            __threadfence();
            unsigned int prev = atomicAdd(&g_done, 1u);
            s_isLast = (prev == (unsigned int)(gridDim.x - 1));
        }
    }
    __syncthreads();

    // ---- fused deterministic final reduction (last block) ----
    if (s_isLast) {
        __threadfence();
        float a = 0.0f;
        for (int i = tid; i < B; i += THREADS) a += g_rowloss[i];
        s_red[tid] = a;
        __syncthreads();
#pragma unroll
        for (int off = THREADS / 2; off; off >>= 1) {
            if (tid < off) s_red[tid] += s_red[tid + off];
            __syncthreads();
        }
        if (tid == 0) {
            out[0] = s_red[0] * (1.0f / (float)B);
            atomicExch(&g_done, 0u);
        }
    }
}

extern "C" void kernel_launch(void* const* d_in, const int* in_sizes, int n_in,
                              void* d_out, int out_size)
{
    const float* logits = (const float*)d_in[0];
    const int*   labels = (const int*)d_in[1];
    const int*   catlab = (const int*)d_in[2];
    const int*   c2c    = (const int*)d_in[3];

    const int B    = in_sizes[1];
    const int V    = in_sizes[0] / B;
    const int ncmd = in_sizes[3];

    hier_loss_fused<<<B, THREADS>>>(logits, labels, catlab, c2c,
                                    (float*)d_out, V, ncmd, B);
}

// round 9
// speedup vs baseline: 1.4756x; 1.0666x over previous
#include <cuda_runtime.h>

#define THREADS 256
#define NWARP (THREADS / 32)
#define TOPK 5
#define NCAT 8
#define CAP 512
#define FULLM 0xffffffffu
#define L2E 1.4426950408889634f
#define LN2 0.6931471805599453f
#define NEG_INF (-__int_as_float(0x7f800000))
#define THRESH 3.25f

__device__ float g_rowloss[8192];
__device__ unsigned int g_done = 0;

__device__ __forceinline__ float ex2f(float x) {
    float y; asm("ex2.approx.ftz.f32 %0, %1;" : "=f"(y) : "f"(x)); return y;
}
__device__ __forceinline__ float lg2f(float x) {
    float y; asm("lg2.approx.ftz.f32 %0, %1;" : "=f"(y) : "f"(x)); return y;
}

__device__ __forceinline__ void insert5(float (&tv)[TOPK], int (&ti)[TOPK], float v, int idx) {
    tv[TOPK - 1] = v; ti[TOPK - 1] = idx;
#pragma unroll
    for (int k = TOPK - 1; k > 0; --k) {
        if (tv[k] > tv[k - 1]) {
            float tf = tv[k]; tv[k] = tv[k - 1]; tv[k - 1] = tf;
            int   tt = ti[k]; ti[k] = ti[k - 1]; ti[k - 1] = tt;
        }
    }
}

__global__ void __launch_bounds__(THREADS, 8)
hier_loss_fused(const float* __restrict__ logits,
                const int* __restrict__ labels,
                const int* __restrict__ catlab,
                const int* __restrict__ c2c,
                float* __restrict__ out,
                int V, int ncmd, int B)
{
    const int b   = blockIdx.x;
    const int tid = threadIdx.x;
    const float* row = logits + (size_t)b * (size_t)V;

    __shared__ int   s_c2c[64];
    __shared__ float s_wS[NWARP];
    __shared__ float s_vals[CAP];
    __shared__ int   s_idx[CAP];
    __shared__ int   s_cnt;
    __shared__ float s_cat[NCAT];
    __shared__ int   s_isLast;
    __shared__ float s_red[THREADS];

    if (tid < 64 && tid < ncmd) s_c2c[tid] = c2c[tid];
    if (tid == 0) s_cnt = 0;
    __syncthreads();

    const float negC = -__ldg(row) * L2E;      // fixed block-wide base (log2 domain)
    float s0 = 0.f, s1 = 0.f;

    const int mis = (int)(((size_t)b * (size_t)V) & 3);
    const int pre = (4 - mis) & 3;
    const int nv4 = (V - pre) >> 2;
    const int nIterV = nv4 / (4 * THREADS);
    const int vecElems = nIterV * 16 * THREADS;
    const float4* __restrict__ p4base = (const float4*)(row + pre);
    const float4* __restrict__ p4 = p4base + tid;

#define PUSH(val, ei)                                                         \
    do {                                                                      \
        if ((val) > THRESH) {                                                 \
            int pos = atomicAdd(&s_cnt, 1);                                   \
            if (pos < CAP) { s_vals[pos] = (val); s_idx[pos] = (ei); }        \
        }                                                                     \
    } while (0)

    // ---- head (pre <= 3 elements) ----
    if (tid < pre) {
        float x = __ldg(row + tid);
        s0 += ex2f(fmaf(x, L2E, negC));
        PUSH(x, tid);
    }

    // ---- main vector loop: 4 x float4 = 16 elements / thread / iter ----
    for (int j = nIterV; j > 0; --j) {
        float4 v0 = __ldg(p4);
        float4 v1 = __ldg(p4 + THREADS);
        float4 v2 = __ldg(p4 + 2 * THREADS);
        float4 v3 = __ldg(p4 + 3 * THREADS);

        float imax = fmaxf(
            fmaxf(fmaxf(fmaxf(v0.x, v0.y), fmaxf(v0.z, v0.w)),
                  fmaxf(fmaxf(v1.x, v1.y), fmaxf(v1.z, v1.w))),
            fmaxf(fmaxf(fmaxf(v2.x, v2.y), fmaxf(v2.z, v2.w)),
                  fmaxf(fmaxf(v3.x, v3.y), fmaxf(v3.z, v3.w))));

        // rare candidate-collection region (indices via pointer diff, cold only)
        if (__any_sync(FULLM, imax > THRESH)) {
            if (imax > THRESH) {
                int e0 = (int)(p4 - p4base);               // float4 index of v0
                int bi0 = pre + 4 * e0;
                int bi1 = bi0 + 4 * THREADS;
                int bi2 = bi0 + 8 * THREADS;
                int bi3 = bi0 + 12 * THREADS;
                PUSH(v0.x, bi0 + 0); PUSH(v0.y, bi0 + 1);
                PUSH(v0.z, bi0 + 2); PUSH(v0.w, bi0 + 3);
                PUSH(v1.x, bi1 + 0); PUSH(v1.y, bi1 + 1);
                PUSH(v1.z, bi1 + 2); PUSH(v1.w, bi1 + 3);
                PUSH(v2.x, bi2 + 0); PUSH(v2.y, bi2 + 1);
                PUSH(v2.z, bi2 + 2); PUSH(v2.w, bi2 + 3);
                PUSH(v3.x, bi3 + 0); PUSH(v3.y, bi3 + 1);
                PUSH(v3.z, bi3 + 2); PUSH(v3.w, bi3 + 3);
            }
        }

        // hot exp-sum: FFMA + MUFU + FADD per element
        s0 += ex2f(fmaf(v0.x, L2E, negC));
        s1 += ex2f(fmaf(v0.y, L2E, negC));
        s0 += ex2f(fmaf(v0.z, L2E, negC));
        s1 += ex2f(fmaf(v0.w, L2E, negC));
        s0 += ex2f(fmaf(v1.x, L2E, negC));
        s1 += ex2f(fmaf(v1.y, L2E, negC));
        s0 += ex2f(fmaf(v1.z, L2E, negC));
        s1 += ex2f(fmaf(v1.w, L2E, negC));
        s0 += ex2f(fmaf(v2.x, L2E, negC));
        s1 += ex2f(fmaf(v2.y, L2E, negC));
        s0 += ex2f(fmaf(v2.z, L2E, negC));
        s1 += ex2f(fmaf(v2.w, L2E, negC));
        s0 += ex2f(fmaf(v3.x, L2E, negC));
        s1 += ex2f(fmaf(v3.y, L2E, negC));
        s0 += ex2f(fmaf(v3.z, L2E, negC));
        s1 += ex2f(fmaf(v3.w, L2E, negC));

        p4 += 4 * THREADS;
    }

    // ---- scalar tail: [pre + vecElems, V) ----
    for (int i = pre + vecElems + tid; i < V; i += THREADS) {
        float x = __ldg(row + i);
        s0 += ex2f(fmaf(x, L2E, negC));
        PUSH(x, i);
    }
#undef PUSH

    // ---- warp reduce s (uniform base for the whole block) ----
    float s = s0 + s1;
#pragma unroll
    for (int off = 16; off; off >>= 1)
        s += __shfl_xor_sync(FULLM, s, off);

    const int lane = tid & 31;
    const int w    = tid >> 5;
    if (lane == 0) s_wS[w] = s;
    __syncthreads();

    // ---- warp 0: top-5 selection + final math ----
    if (w == 0) {
        float tv[TOPK]; int ti[TOPK];
#pragma unroll
        for (int k = 0; k < TOPK; ++k) { tv[k] = NEG_INF; ti[k] = 0; }

        int cnt = s_cnt;
        if (cnt >= TOPK && cnt <= CAP) {
            for (int base = 0; base < cnt; base += 32) {
                int i = base + lane;
                float x = (i < cnt) ? s_vals[i] : NEG_INF;
                int  id = (i < cnt) ? s_idx[i]  : 0;
                unsigned bal = __ballot_sync(FULLM, x > tv[TOPK - 1]);
                while (bal) {
                    int L = __ffs(bal) - 1; bal &= bal - 1;
                    float xv = __shfl_sync(FULLM, x, L);
                    int   iv = __shfl_sync(FULLM, id, L);
                    if (xv > tv[TOPK - 1]) insert5(tv, ti, xv, iv);
                }
            }
        } else {
            // exact fallback (astronomically rare): full-row online top-5
            for (int i0 = 0; i0 < V; i0 += 32) {
                int i = i0 + lane;
                float x = (i < V) ? __ldg(row + i) : NEG_INF;
                unsigned bal = __ballot_sync(FULLM, x > tv[TOPK - 1]);
                while (bal) {
                    int L = __ffs(bal) - 1; bal &= bal - 1;
                    float xv = __shfl_sync(FULLM, x, L);
                    if (xv > tv[TOPK - 1]) insert5(tv, ti, xv, i0 + L);
                }
            }
        }

        if (lane == 0) {
            float sf = 0.0f;
            for (int ww = 0; ww < NWARP; ++ww) sf += s_wS[ww];

            float lse  = (-negC + lg2f(sf)) * LN2;
            int   lab  = __ldg(labels + b);
            float xlab = __ldg(row + lab);
            float nll_cmd = lse - xlab;

#pragma unroll
            for (int c = 0; c < NCAT; ++c) s_cat[c] = 0.0f;
#pragma unroll
            for (int k = 0; k < TOPK; ++k)
                s_cat[s_c2c[ti[k] % ncmd]] += tv[k];

            float mxc = s_cat[0];
#pragma unroll
            for (int c = 1; c < NCAT; ++c) mxc = fmaxf(mxc, s_cat[c]);
            float ssum = 0.0f;
#pragma unroll
            for (int c = 0; c < NCAT; ++c) ssum += ex2f((s_cat[c] - mxc) * L2E);
            int   cl = __ldg(catlab + b);
            float nll_cat = lg2f(ssum) * LN2 + mxc - s_cat[cl];

            g_rowloss[b] = 0.6f * nll_cmd + 0.4f * nll_cat;

            __threadfence();
            unsigned int prev = atomicAdd(&g_done, 1u);
            s_isLast = (prev == (unsigned int)(gridDim.x - 1));
        }
    }
    __syncthreads();

    // ---- fused deterministic final reduction (last block) ----
    if (s_isLast) {
        __threadfence();
        float a = 0.0f;
        for (int i = tid; i < B; i += THREADS) a += g_rowloss[i];
        s_red[tid] = a;
        __syncthreads();
#pragma unroll
        for (int off = THREADS / 2; off; off >>= 1) {
            if (tid < off) s_red[tid] += s_red[tid + off];
            __syncthreads();
        }
        if (tid == 0) {
            out[0] = s_red[0] * (1.0f / (float)B);
            atomicExch(&g_done, 0u);
        }
    }
}

extern "C" void kernel_launch(void* const* d_in, const int* in_sizes, int n_in,
                              void* d_out, int out_size)
{
    const float* logits = (const float*)d_in[0];
    const int*   labels = (const int*)d_in[1];
    const int*   catlab = (const int*)d_in[2];
    const int*   c2c    = (const int*)d_in[3];

    const int B    = in_sizes[1];
    const int V    = in_sizes[0] / B;
    const int ncmd = in_sizes[3];

    hier_loss_fused<<<B, THREADS>>>(logits, labels, catlab, c2c,
                                    (float*)d_out, V, ncmd, B);
}

// round 10
// speedup vs baseline: 1.4791x; 1.0024x over previous
#include <cuda_runtime.h>

#define THREADS 256
#define NWARP (THREADS / 32)
#define TOPK 5
#define NCAT 8
#define CAP 512
#define GRID 1216           /* 152 SMs x 8 CTAs */
#define FULLM 0xffffffffu
#define L2E 1.4426950408889634f
#define LN2 0.6931471805599453f
#define NEG_INF (-__int_as_float(0x7f800000))
#define THRESH 3.25f

__device__ float g_rowloss[8192];
__device__ unsigned int g_done = 0;

__device__ __forceinline__ float ex2f(float x) {
    float y; asm("ex2.approx.ftz.f32 %0, %1;" : "=f"(y) : "f"(x)); return y;
}
__device__ __forceinline__ float lg2f(float x) {
    float y; asm("lg2.approx.ftz.f32 %0, %1;" : "=f"(y) : "f"(x)); return y;
}

__device__ __forceinline__ void insert5(float (&tv)[TOPK], int (&ti)[TOPK], float v, int idx) {
    tv[TOPK - 1] = v; ti[TOPK - 1] = idx;
#pragma unroll
    for (int k = TOPK - 1; k > 0; --k) {
        if (tv[k] > tv[k - 1]) {
            float tf = tv[k]; tv[k] = tv[k - 1]; tv[k - 1] = tf;
            int   tt = ti[k]; ti[k] = ti[k - 1]; ti[k - 1] = tt;
        }
    }
}

__global__ void __launch_bounds__(THREADS, 8)
hier_loss_fused(const float* __restrict__ logits,
                const int* __restrict__ labels,
                const int* __restrict__ catlab,
                const int* __restrict__ c2c,
                float* __restrict__ out,
                int V, int ncmd, int B)
{
    const int tid  = threadIdx.x;
    const int lane = tid & 31;
    const int w    = tid >> 5;

    __shared__ int   s_c2c[64];
    __shared__ float s_wS[NWARP];
    __shared__ float s_vals[CAP];
    __shared__ int   s_idx[CAP];
    __shared__ int   s_cnt;
    __shared__ float s_cat[NCAT];
    __shared__ int   s_isLast;
    __shared__ float s_red[THREADS];

    if (tid < 64 && tid < ncmd) s_c2c[tid] = c2c[tid];
    if (tid == 0) s_cnt = 0;
    __syncthreads();

    // ================= persistent row loop =================
    for (int b = blockIdx.x; b < B; b += gridDim.x) {
        const float* row = logits + (size_t)b * (size_t)V;

        const float negC = -__ldg(row) * L2E;  // block-wide base (log2 domain)
        float s0 = 0.f, s1 = 0.f;

        const int mis = (int)(((size_t)b * (size_t)V) & 3);
        const int pre = (4 - mis) & 3;
        const int nv4 = (V - pre) >> 2;
        const int nIterV = nv4 / (4 * THREADS);
        const int vecElems = nIterV * 16 * THREADS;
        const float4* __restrict__ p4base = (const float4*)(row + pre);
        const float4* __restrict__ p4 = p4base + tid;

#define PUSH(val, ei)                                                         \
        do {                                                                  \
            if ((val) > THRESH) {                                             \
                int pos = atomicAdd(&s_cnt, 1);                               \
                if (pos < CAP) { s_vals[pos] = (val); s_idx[pos] = (ei); }    \
            }                                                                 \
        } while (0)

        // ---- head (pre <= 3 elements) ----
        if (tid < pre) {
            float x = __ldg(row + tid);
            s0 += ex2f(fmaf(x, L2E, negC));
            PUSH(x, tid);
        }

        // ---- main vector loop: 4 x float4 = 16 elements / thread / iter ----
        for (int j = nIterV; j > 0; --j) {
            float4 v0 = __ldcs(p4);
            float4 v1 = __ldcs(p4 + THREADS);
            float4 v2 = __ldcs(p4 + 2 * THREADS);
            float4 v3 = __ldcs(p4 + 3 * THREADS);

            float imax = fmaxf(
                fmaxf(fmaxf(fmaxf(v0.x, v0.y), fmaxf(v0.z, v0.w)),
                      fmaxf(fmaxf(v1.x, v1.y), fmaxf(v1.z, v1.w))),
                fmaxf(fmaxf(fmaxf(v2.x, v2.y), fmaxf(v2.z, v2.w)),
                      fmaxf(fmaxf(v3.x, v3.y), fmaxf(v3.z, v3.w))));

            // rare candidate-collection region (cold)
            if (__any_sync(FULLM, imax > THRESH)) {
                if (imax > THRESH) {
                    int e0 = (int)(p4 - p4base);
                    int bi0 = pre + 4 * e0;
                    int bi1 = bi0 + 4 * THREADS;
                    int bi2 = bi0 + 8 * THREADS;
                    int bi3 = bi0 + 12 * THREADS;
                    PUSH(v0.x, bi0 + 0); PUSH(v0.y, bi0 + 1);
                    PUSH(v0.z, bi0 + 2); PUSH(v0.w, bi0 + 3);
                    PUSH(v1.x, bi1 + 0); PUSH(v1.y, bi1 + 1);
                    PUSH(v1.z, bi1 + 2); PUSH(v1.w, bi1 + 3);
                    PUSH(v2.x, bi2 + 0); PUSH(v2.y, bi2 + 1);
                    PUSH(v2.z, bi2 + 2); PUSH(v2.w, bi2 + 3);
                    PUSH(v3.x, bi3 + 0); PUSH(v3.y, bi3 + 1);
                    PUSH(v3.z, bi3 + 2); PUSH(v3.w, bi3 + 3);
                }
            }

            // hot exp-sum
            s0 += ex2f(fmaf(v0.x, L2E, negC));
            s1 += ex2f(fmaf(v0.y, L2E, negC));
            s0 += ex2f(fmaf(v0.z, L2E, negC));
            s1 += ex2f(fmaf(v0.w, L2E, negC));
            s0 += ex2f(fmaf(v1.x, L2E, negC));
            s1 += ex2f(fmaf(v1.y, L2E, negC));
            s0 += ex2f(fmaf(v1.z, L2E, negC));
            s1 += ex2f(fmaf(v1.w, L2E, negC));
            s0 += ex2f(fmaf(v2.x, L2E, negC));
            s1 += ex2f(fmaf(v2.y, L2E, negC));
            s0 += ex2f(fmaf(v2.z, L2E, negC));
            s1 += ex2f(fmaf(v2.w, L2E, negC));
            s0 += ex2f(fmaf(v3.x, L2E, negC));
            s1 += ex2f(fmaf(v3.y, L2E, negC));
            s0 += ex2f(fmaf(v3.z, L2E, negC));
            s1 += ex2f(fmaf(v3.w, L2E, negC));

            p4 += 4 * THREADS;
        }

        // ---- scalar tail ----
        for (int i = pre + vecElems + tid; i < V; i += THREADS) {
            float x = __ldg(row + i);
            s0 += ex2f(fmaf(x, L2E, negC));
            PUSH(x, i);
        }
#undef PUSH

        // ---- warp reduce (uniform base) ----
        float s = s0 + s1;
#pragma unroll
        for (int off = 16; off; off >>= 1)
            s += __shfl_xor_sync(FULLM, s, off);
        if (lane == 0) s_wS[w] = s;
        __syncthreads();                       // (A) pushes + partial sums visible

        // ---- warp 0: top-5 + row loss ----
        if (w == 0) {
            float tv[TOPK]; int ti[TOPK];
#pragma unroll
            for (int k = 0; k < TOPK; ++k) { tv[k] = NEG_INF; ti[k] = 0; }

            int cnt = s_cnt;
            __syncwarp();
            if (cnt >= TOPK && cnt <= CAP) {
                for (int base = 0; base < cnt; base += 32) {
                    int i = base + lane;
                    float x = (i < cnt) ? s_vals[i] : NEG_INF;
                    int  id = (i < cnt) ? s_idx[i]  : 0;
                    unsigned bal = __ballot_sync(FULLM, x > tv[TOPK - 1]);
                    while (bal) {
                        int L = __ffs(bal) - 1; bal &= bal - 1;
                        float xv = __shfl_sync(FULLM, x, L);
                        int   iv = __shfl_sync(FULLM, id, L);
                        if (xv > tv[TOPK - 1]) insert5(tv, ti, xv, iv);
                    }
                }
            } else {
                // exact fallback (astronomically rare)
                for (int i0 = 0; i0 < V; i0 += 32) {
                    int i = i0 + lane;
                    float x = (i < V) ? __ldg(row + i) : NEG_INF;
                    unsigned bal = __ballot_sync(FULLM, x > tv[TOPK - 1]);
                    while (bal) {
                        int L = __ffs(bal) - 1; bal &= bal - 1;
                        float xv = __shfl_sync(FULLM, x, L);
                        if (xv > tv[TOPK - 1]) insert5(tv, ti, xv, i0 + L);
                    }
                }
            }

            if (lane == 0) {
                float sf = 0.0f;
                for (int ww = 0; ww < NWARP; ++ww) sf += s_wS[ww];

                float lse  = (-negC + lg2f(sf)) * LN2;
                int   lab  = __ldg(labels + b);
                float xlab = __ldg(row + lab);
                float nll_cmd = lse - xlab;

#pragma unroll
                for (int c = 0; c < NCAT; ++c) s_cat[c] = 0.0f;
#pragma unroll
                for (int k = 0; k < TOPK; ++k)
                    s_cat[s_c2c[ti[k] % ncmd]] += tv[k];

                float mxc = s_cat[0];
#pragma unroll
                for (int c = 1; c < NCAT; ++c) mxc = fmaxf(mxc, s_cat[c]);
                float ssum = 0.0f;
#pragma unroll
                for (int c = 0; c < NCAT; ++c) ssum += ex2f((s_cat[c] - mxc) * L2E);
                int   cl = __ldg(catlab + b);
                float nll_cat = lg2f(ssum) * LN2 + mxc - s_cat[cl];

                g_rowloss[b] = 0.6f * nll_cmd + 0.4f * nll_cat;
                s_cnt = 0;                    // reset for next row (sole reader)
            }
        }
        __syncthreads();                       // (B) epilogue + reset done
    }
    // ================= end row loop =================

    // completion protocol: once per CTA
    if (tid == 0) {
        __threadfence();
        unsigned int prev = atomicAdd(&g_done, 1u);
        s_isLast = (prev == (unsigned int)(gridDim.x - 1));
    }
    __syncthreads();

    if (s_isLast) {
        __threadfence();
        float a = 0.0f;
        for (int i = tid; i < B; i += THREADS) a += g_rowloss[i];
        s_red[tid] = a;
        __syncthreads();
#pragma unroll
        for (int off = THREADS / 2; off; off >>= 1) {
            if (tid < off) s_red[tid] += s_red[tid + off];
            __syncthreads();
        }
        if (tid == 0) {
            out[0] = s_red[0] * (1.0f / (float)B);
            atomicExch(&g_done, 0u);
        }
    }
}

extern "C" void kernel_launch(void* const* d_in, const int* in_sizes, int n_in,
                              void* d_out, int out_size)
{
    const float* logits = (const float*)d_in[0];
    const int*   labels = (const int*)d_in[1];
    const int*   catlab = (const int*)d_in[2];
    const int*   c2c    = (const int*)d_in[3];

    const int B    = in_sizes[1];
    const int V    = in_sizes[0] / B;
    const int ncmd = in_sizes[3];

    int grid = GRID < B ? GRID : B;
    hier_loss_fused<<<grid, THREADS>>>(logits, labels, catlab, c2c,
                                       (float*)d_out, V, ncmd, B);
}